// round 5
// baseline (speedup 1.0000x reference)
#include <cuda_runtime.h>
#include <cuda_bf16.h>
#include <cstdint>
#include <cstddef>

#define NROW 65536

__device__ float g_cbuf0[768 * 64];
__device__ float g_cbuf1[768 * 64];
__device__ float g_feat[2048];
__device__ float g_c1[1024];
__device__ float g_A1[256 * 1024];
__device__ float g_B1[256 * 1024];
__device__ float g_A2[256 * 512];
__device__ float g_B2[256 * 512];
__device__ float g_wm1F[8 * 512 * 512];
__device__ float g_wm1G[8 * 512 * 512];
__device__ float g_wm2F[8 * 256 * 256];
__device__ float g_wm2G[8 * 256 * 256];
__device__ float g_mid[(size_t)NROW * 1024];
__device__ float g_h[(size_t)NROW * 512];

__device__ __forceinline__ float lrelu(float x) { return x > 0.f ? x : 0.01f * x; }
__device__ __forceinline__ uint32_t rna(float x) {
    uint32_t u; asm("cvt.rna.tf32.f32 %0,%1;" : "=r"(u) : "f"(x)); return u;
}
__device__ __forceinline__ void cp16(uint32_t s, const float* g) {
    asm volatile("cp.async.cg.shared.global [%0], [%1], 16;\n" :: "r"(s), "l"(g) : "memory");
}
__device__ __forceinline__ void mma_tf32(float* c, const uint32_t* a, const uint32_t* b) {
    asm volatile(
        "mma.sync.aligned.m16n8k8.row.col.f32.tf32.tf32.f32 "
        "{%0,%1,%2,%3},{%4,%5,%6,%7},{%8,%9},{%0,%1,%2,%3};\n"
        : "+f"(c[0]), "+f"(c[1]), "+f"(c[2]), "+f"(c[3])
        : "r"(a[0]), "r"(a[1]), "r"(a[2]), "r"(a[3]), "r"(b[0]), "r"(b[1]));
}

// -------- grouped 3x3 conv + lrelu: one block per output channel ---------------------
__global__ void k_conv(const float* __restrict__ in, const float* __restrict__ w,
                       const float* __restrict__ bias, float* __restrict__ out,
                       int CinG, int CoutPerG, int Hin, int Hout, int pad)
{
    __shared__ float sw[6912];
    __shared__ float sp[16 * 100];
    __shared__ float red[256];
    int o = blockIdx.x, t = threadIdx.x;
    int g = o / CoutPerG;
    const float* inG = in + (size_t)g * CinG * Hin * Hin;
    int nW = CinG * 9;
    for (int i = t; i < nW; i += 256) sw[i] = w[(size_t)o * nW + i];
    int npix = Hout * Hout;
    int pix = t & 63, ph = t >> 6;
    int y = pix / Hout, x = pix - y * Hout;
    bool act = pix < npix;
    int HP = Hin + 2 * pad, npl = HP * HP, nCh = CinG >> 4;
    float acc = 0.f;
    for (int ch = 0; ch < nCh; ++ch) {
        __syncthreads();
        for (int i = t; i < 16 * npl; i += 256) {
            int ci = i / npl, rem = i - ci * npl;
            int yy = rem / HP, xx = rem - yy * HP;
            int ys = yy - pad, xs = xx - pad;
            float v = 0.f;
            if (ys >= 0 && ys < Hin && xs >= 0 && xs < Hin)
                v = inG[(size_t)(ch * 16 + ci) * Hin * Hin + ys * Hin + xs];
            sp[ci * 100 + yy * HP + xx] = v;
        }
        __syncthreads();
        if (act && ((ch & 3) == ph)) {
            for (int ci = 0; ci < 16; ++ci) {
                const float* wp = &sw[(ch * 16 + ci) * 9];
                const float* pp = &sp[ci * 100 + y * HP + x];
                acc += wp[0]*pp[0]      + wp[1]*pp[1]      + wp[2]*pp[2]
                     + wp[3]*pp[HP]     + wp[4]*pp[HP+1]   + wp[5]*pp[HP+2]
                     + wp[6]*pp[2*HP]   + wp[7]*pp[2*HP+1] + wp[8]*pp[2*HP+2];
            }
        }
    }
    __syncthreads();
    red[t] = acc;
    __syncthreads();
    if (ph == 0 && act) {
        float s = red[pix] + red[pix+64] + red[pix+128] + red[pix+192] + bias[o];
        out[(size_t)o * npix + pix] = lrelu(s);
    }
}

// -------- c1 = W1[:,32:] @ feat + b1 -------------------------------------------------
__global__ void k_c1(const float* __restrict__ w1, const float* __restrict__ b1,
                     const float* __restrict__ feat, float* __restrict__ c1)
{
    __shared__ float sf[2048];
    for (int i = threadIdx.x; i < 2048; i += 256) sf[i] = feat[i];
    __syncthreads();
    int o = blockIdx.x * 8 + (threadIdx.x >> 5);
    int lane = threadIdx.x & 31;
    const float* row = w1 + (size_t)o * 2080 + 32;
    float s = 0.f;
    for (int k = lane; k < 2048; k += 32) s += row[k] * sf[k];
    #pragma unroll
    for (int off = 16; off; off >>= 1) s += __shfl_xor_sync(0xffffffffu, s, off);
    if (lane == 0) c1[o] = s + b1[o];
}

// -------- separable sin tables -------------------------------------------------------
__global__ void k_tab(const float* __restrict__ w, int ld, const float* __restrict__ base,
                      float* __restrict__ A, float* __restrict__ B, int width)
{
    __shared__ float s[16];
    int i = blockIdx.x;
    if (threadIdx.x < 16) {
        double arg = (double)(i - 128) * 3.14159265358979323846 / 256.0
                   * exp2((double)threadIdx.x * 0.5);
        s[threadIdx.x] = (float)sin(arg);
    }
    __syncthreads();
    for (int o = threadIdx.x; o < width; o += 256) {
        const float* wr = w + (size_t)o * ld;
        float sa = base[o], sb = 0.f;
        #pragma unroll
        for (int f = 0; f < 16; ++f) {
            sa += s[f] * wr[2 * f];
            sb += s[f] * wr[2 * f + 1];
        }
        A[(size_t)i * width + o] = sa;
        B[(size_t)i * width + o] = sb;
    }
}

// -------- weight-norm: w = v * g / ||v||  (L matrices of [N][K]) ---------------------
__global__ void k_wnorm(const float* __restrict__ v, const float* __restrict__ g,
                        float* __restrict__ out, int N, int K)
{
    __shared__ float red[256];
    int b = blockIdx.x;                    // b = l*N + n
    const float* vr = v + (size_t)b * K;
    float ss = 0.f;
    for (int k = threadIdx.x; k < K; k += 256) { float t = vr[k]; ss += t * t; }
    red[threadIdx.x] = ss;
    __syncthreads();
    for (int off = 128; off; off >>= 1) {
        if (threadIdx.x < off) red[threadIdx.x] += red[threadIdx.x + off];
        __syncthreads();
    }
    float sc = g[b] / sqrtf(red[0]);
    float* orow = out + (size_t)b * K;
    for (int k = threadIdx.x; k < K; k += 256) orow[k] = vr[k] * sc;
}

// -------- mid init: lrelu(A1[i]+B1[j]) ------------------------------------------------
__global__ void k_midinit(const float* __restrict__ A, const float* __restrict__ B,
                          float* __restrict__ mid)
{
    size_t idx = (size_t)blockIdx.x * 256 + threadIdx.x;
    int r = (int)(idx >> 10), o = (int)(idx & 1023);
    int i = r >> 8, j = r & 255;
    mid[idx] = lrelu(A[(size_t)i * 1024 + o] + B[(size_t)j * 1024 + o]);
}

// -------- tf32 GEMM: C(M x N) = X(M x K, ld ldx) * W(N x K, ld ldw)^T ----------------
// mode 1: out[r][n] += lrelu(acc + bias[n])          (residual coupling)
// mode 2: out[r][n]  = lrelu(acc + tA[i][n]+tB[j][n]) (w2 layer, tables fold b2/grid)
__global__ void __launch_bounds__(256, 2)
k_gemm(const float* __restrict__ X, int ldx, const float* __restrict__ W, int ldw,
       const float* __restrict__ bias, float* __restrict__ out, int ldo,
       int N, int K, int mode, const float* __restrict__ tA, const float* __restrict__ tB)
{
    __shared__ float sA[128 * 20];
    __shared__ float sB[64 * 20];
    int tid = threadIdx.x;
    int m0 = blockIdx.y * 128, n0 = blockIdx.x * 64;
    int wid = tid >> 5, lane = tid & 31;
    int wm = wid & 3, wn = wid >> 2;
    int gq = lane >> 2, tq = lane & 3;
    uint32_t sAu = (uint32_t)__cvta_generic_to_shared(sA);
    uint32_t sBu = (uint32_t)__cvta_generic_to_shared(sB);

    float c[2][4][4];
    #pragma unroll
    for (int a = 0; a < 2; ++a)
        #pragma unroll
        for (int b = 0; b < 4; ++b)
            #pragma unroll
            for (int e = 0; e < 4; ++e) c[a][b][e] = 0.f;

    for (int kt = 0; kt < K; kt += 16) {
        __syncthreads();
        #pragma unroll
        for (int i = 0; i < 2; ++i) {
            int idx = tid + i * 256;
            int r = idx >> 2, cc = (idx & 3) << 2;
            cp16(sAu + (uint32_t)(r * 20 + cc) * 4, X + (size_t)(m0 + r) * ldx + kt + cc);
        }
        {
            int r = tid >> 2, cc = (tid & 3) << 2;
            cp16(sBu + (uint32_t)(r * 20 + cc) * 4, W + (size_t)(n0 + r) * ldw + kt + cc);
        }
        asm volatile("cp.async.commit_group;\n" ::: "memory");
        asm volatile("cp.async.wait_group 0;\n" ::: "memory");
        __syncthreads();

        #pragma unroll
        for (int ks = 0; ks < 16; ks += 8) {
            uint32_t au[2][4], bu[4][2];
            #pragma unroll
            for (int mf = 0; mf < 2; ++mf) {
                int rb = (wm * 32 + mf * 16 + gq) * 20 + ks + tq;
                au[mf][0] = rna(sA[rb]);
                au[mf][1] = rna(sA[rb + 8 * 20]);
                au[mf][2] = rna(sA[rb + 4]);
                au[mf][3] = rna(sA[rb + 8 * 20 + 4]);
            }
            #pragma unroll
            for (int nf = 0; nf < 4; ++nf) {
                int rb = (wn * 32 + nf * 8 + gq) * 20 + ks + tq;
                bu[nf][0] = rna(sB[rb]);
                bu[nf][1] = rna(sB[rb + 4]);
            }
            #pragma unroll
            for (int mf = 0; mf < 2; ++mf)
                #pragma unroll
                for (int nf = 0; nf < 4; ++nf)
                    mma_tf32(c[mf][nf], au[mf], bu[nf]);
        }
    }

    #pragma unroll
    for (int mf = 0; mf < 2; ++mf)
        #pragma unroll
        for (int nf = 0; nf < 4; ++nf)
            #pragma unroll
            for (int e = 0; e < 4; ++e) {
                int r = m0 + wm * 32 + mf * 16 + gq + (e >> 1) * 8;
                int cn = n0 + wn * 32 + nf * 8 + tq * 2 + (e & 1);
                float acc = c[mf][nf][e];
                size_t oi = (size_t)r * ldo + cn;
                if (mode == 1) {
                    out[oi] += lrelu(acc + bias[cn]);
                } else {
                    float v = acc + tA[(size_t)(r >> 8) * N + cn] + tB[(size_t)(r & 255) * N + cn];
                    out[oi] = lrelu(v);
                }
            }
}

// -------- final: sigmoid(h @ w3.T + b3)*1.1-0.05, CHW layout -------------------------
__global__ void k_final(const float* __restrict__ h, const float* __restrict__ w3,
                        const float* __restrict__ b3, float* __restrict__ out)
{
    __shared__ float w3s[3 * 512];
    for (int i = threadIdx.x; i < 1536; i += 256) w3s[i] = w3[i];
    __syncthreads();
    int pix = blockIdx.x * 8 + (threadIdx.x >> 5);
    int lane = threadIdx.x & 31;
    const float* hr = h + (size_t)pix * 512;
    float a0 = 0.f, a1 = 0.f, a2 = 0.f;
    for (int k = lane; k < 512; k += 32) {
        float hv = hr[k];
        a0 += hv * w3s[k];
        a1 += hv * w3s[512 + k];
        a2 += hv * w3s[1024 + k];
    }
    #pragma unroll
    for (int off = 16; off; off >>= 1) {
        a0 += __shfl_xor_sync(0xffffffffu, a0, off);
        a1 += __shfl_xor_sync(0xffffffffu, a1, off);
        a2 += __shfl_xor_sync(0xffffffffu, a2, off);
    }
    if (lane == 0) {
        float z[3] = {a0 + b3[0], a1 + b3[1], a2 + b3[2]};
        #pragma unroll
        for (int cch = 0; cch < 3; ++cch) {
            float s = 1.f / (1.f + expf(-z[cch]));
            out[(size_t)cch * NROW + pix] = s * 1.1f - 0.05f;
        }
    }
}

extern "C" void kernel_launch(void* const* d_in, const int* in_sizes, int n_in,
                              void* d_out, int out_size)
{
    (void)in_sizes; (void)n_in; (void)out_size;
    const float* feature = (const float*)d_in[0];
    const float *cw1=(const float*)d_in[1], *cb1=(const float*)d_in[2];
    const float *cw2=(const float*)d_in[3], *cb2=(const float*)d_in[4];
    const float *cw3=(const float*)d_in[5], *cb3=(const float*)d_in[6];
    const float *cw4=(const float*)d_in[7], *cb4=(const float*)d_in[8];
    const float *cw5=(const float*)d_in[9], *cb5=(const float*)d_in[10];
    const float *w1=(const float*)d_in[11], *b1=(const float*)d_in[12];
    const float *m1_vf=(const float*)d_in[13], *m1_gf=(const float*)d_in[14], *m1_bf=(const float*)d_in[15];
    const float *m1_vg=(const float*)d_in[16], *m1_gg=(const float*)d_in[17], *m1_bg=(const float*)d_in[18];
    const float *w2=(const float*)d_in[19], *b2=(const float*)d_in[20];
    const float *m2_vf=(const float*)d_in[21], *m2_gf=(const float*)d_in[22], *m2_bf=(const float*)d_in[23];
    const float *m2_vg=(const float*)d_in[24], *m2_gg=(const float*)d_in[25], *m2_bg=(const float*)d_in[26];
    const float *w3=(const float*)d_in[27], *b3=(const float*)d_in[28];
    float* out = (float*)d_out;

    float *cb0p, *cb1p, *featp, *c1p, *A1p, *B1p, *A2p, *B2p;
    float *w1F, *w1G, *w2F, *w2G, *midp, *hp;
    cudaGetSymbolAddress((void**)&cb0p, g_cbuf0);
    cudaGetSymbolAddress((void**)&cb1p, g_cbuf1);
    cudaGetSymbolAddress((void**)&featp, g_feat);
    cudaGetSymbolAddress((void**)&c1p, g_c1);
    cudaGetSymbolAddress((void**)&A1p, g_A1);
    cudaGetSymbolAddress((void**)&B1p, g_B1);
    cudaGetSymbolAddress((void**)&A2p, g_A2);
    cudaGetSymbolAddress((void**)&B2p, g_B2);
    cudaGetSymbolAddress((void**)&w1F, g_wm1F);
    cudaGetSymbolAddress((void**)&w1G, g_wm1G);
    cudaGetSymbolAddress((void**)&w2F, g_wm2F);
    cudaGetSymbolAddress((void**)&w2G, g_wm2G);
    cudaGetSymbolAddress((void**)&midp, g_mid);
    cudaGetSymbolAddress((void**)&hp, g_h);

    // convs: feature[1792,8,8] -> ... -> feat[2048]
    k_conv<<<768, 256>>>(feature, cw1, cb1, cb0p, 448, 192, 8, 8, 1);
    k_conv<<<768, 256>>>(cb0p, cw2, cb2, cb1p, 256, 256, 8, 8, 1);
    k_conv<<<768, 256>>>(cb1p, cw3, cb3, cb0p, 384, 384, 8, 8, 1);
    k_conv<<<768, 256>>>(cb0p, cw4, cb4, cb1p, 256, 256, 8, 6, 0);
    k_conv<<<128, 256>>>(cb1p, cw5, cb5, featp, 768, 128, 6, 4, 0);

    k_c1<<<128, 256>>>(w1, b1, featp, c1p);
    k_tab<<<256, 256>>>(w1, 2080, c1p, A1p, B1p, 1024);
    k_tab<<<256, 256>>>(w2, 1056, b2, A2p, B2p, 512);

    k_wnorm<<<8 * 512, 256>>>(m1_vf, m1_gf, w1F, 512, 512);
    k_wnorm<<<8 * 512, 256>>>(m1_vg, m1_gg, w1G, 512, 512);
    k_wnorm<<<8 * 256, 256>>>(m2_vf, m2_gf, w2F, 256, 256);
    k_wnorm<<<8 * 256, 256>>>(m2_vg, m2_gg, w2G, 256, 256);

    k_midinit<<<(NROW * 1024) / 256, 256>>>(A1p, B1p, midp);

    dim3 blk(256);
    dim3 g512(8, 512), g256(4, 512);
    for (int l = 0; l < 8; ++l) {
        k_gemm<<<g512, blk>>>(midp + 512, 1024, w1F + (size_t)l * 512 * 512, 512,
                              m1_bf + l * 512, midp, 1024, 512, 512, 1, nullptr, nullptr);
        k_gemm<<<g512, blk>>>(midp, 1024, w1G + (size_t)l * 512 * 512, 512,
                              m1_bg + l * 512, midp + 512, 1024, 512, 512, 1, nullptr, nullptr);
    }
    k_gemm<<<g512, blk>>>(midp, 1024, w2 + 32, 1056, nullptr, hp, 512,
                          512, 1024, 2, A2p, B2p);
    for (int l = 0; l < 8; ++l) {
        k_gemm<<<g256, blk>>>(hp + 256, 512, w2F + (size_t)l * 256 * 256, 256,
                              m2_bf + l * 256, hp, 512, 256, 256, 1, nullptr, nullptr);
        k_gemm<<<g256, blk>>>(hp, 512, w2G + (size_t)l * 256 * 256, 256,
                              m2_bg + l * 256, hp + 256, 512, 256, 256, 1, nullptr, nullptr);
    }
    k_final<<<NROW / 8, 256>>>(hp, w3, b3, out);
}

// round 6
// speedup vs baseline: 1.6167x; 1.6167x over previous
#include <cuda_runtime.h>
#include <cuda_bf16.h>
#include <cstdint>
#include <cstddef>

#define NROW 65536

__device__ float g_cbuf0[768 * 64];
__device__ float g_cbuf1[768 * 64];
__device__ float g_feat[2048];
__device__ float g_c1[1024];
__device__ float g_A1[256 * 1024];
__device__ float g_B1[256 * 1024];
__device__ float g_A2[256 * 512];
__device__ float g_B2[256 * 512];
__device__ float g_wm1F[8 * 512 * 512];
__device__ float g_wm1G[8 * 512 * 512];
__device__ float g_wm2F[8 * 256 * 256];
__device__ float g_wm2G[8 * 256 * 256];
__device__ float g_mid[(size_t)NROW * 1024];
__device__ float g_h[(size_t)NROW * 512];

__device__ __forceinline__ float lrelu(float x) { return x > 0.f ? x : 0.01f * x; }
__device__ __forceinline__ uint32_t rna(float x) {
    uint32_t u; asm("cvt.rna.tf32.f32 %0,%1;" : "=r"(u) : "f"(x)); return u;
}
__device__ __forceinline__ void cp16(uint32_t s, const float* g) {
    asm volatile("cp.async.cg.shared.global [%0], [%1], 16;\n" :: "r"(s), "l"(g) : "memory");
}
__device__ __forceinline__ void cp_commit() { asm volatile("cp.async.commit_group;\n" ::: "memory"); }
__device__ __forceinline__ void cp_wait0()  { asm volatile("cp.async.wait_group 0;\n" ::: "memory"); }
__device__ __forceinline__ void cp_wait1()  { asm volatile("cp.async.wait_group 1;\n" ::: "memory"); }
__device__ __forceinline__ void mma_tf32(float* c, const uint32_t* a, const uint32_t* b) {
    asm volatile(
        "mma.sync.aligned.m16n8k8.row.col.f32.tf32.tf32.f32 "
        "{%0,%1,%2,%3},{%4,%5,%6,%7},{%8,%9},{%0,%1,%2,%3};\n"
        : "+f"(c[0]), "+f"(c[1]), "+f"(c[2]), "+f"(c[3])
        : "r"(a[0]), "r"(a[1]), "r"(a[2]), "r"(a[3]), "r"(b[0]), "r"(b[1]));
}

// -------- grouped 3x3 conv + lrelu: one block per output channel ---------------------
__global__ void k_conv(const float* __restrict__ in, const float* __restrict__ w,
                       const float* __restrict__ bias, float* __restrict__ out,
                       int CinG, int CoutPerG, int Hin, int Hout, int pad)
{
    __shared__ float sw[6912];
    __shared__ float sp[16 * 100];
    __shared__ float red[256];
    int o = blockIdx.x, t = threadIdx.x;
    int g = o / CoutPerG;
    const float* inG = in + (size_t)g * CinG * Hin * Hin;
    int nW = CinG * 9;
    for (int i = t; i < nW; i += 256) sw[i] = w[(size_t)o * nW + i];
    int npix = Hout * Hout;
    int pix = t & 63, ph = t >> 6;
    int y = pix / Hout, x = pix - y * Hout;
    bool act = pix < npix;
    int HP = Hin + 2 * pad, npl = HP * HP, nCh = CinG >> 4;
    float acc = 0.f;
    for (int ch = 0; ch < nCh; ++ch) {
        __syncthreads();
        for (int i = t; i < 16 * npl; i += 256) {
            int ci = i / npl, rem = i - ci * npl;
            int yy = rem / HP, xx = rem - yy * HP;
            int ys = yy - pad, xs = xx - pad;
            float v = 0.f;
            if (ys >= 0 && ys < Hin && xs >= 0 && xs < Hin)
                v = inG[(size_t)(ch * 16 + ci) * Hin * Hin + ys * Hin + xs];
            sp[ci * 100 + yy * HP + xx] = v;
        }
        __syncthreads();
        if (act && ((ch & 3) == ph)) {
            for (int ci = 0; ci < 16; ++ci) {
                const float* wp = &sw[(ch * 16 + ci) * 9];
                const float* pp = &sp[ci * 100 + y * HP + x];
                acc += wp[0]*pp[0]      + wp[1]*pp[1]      + wp[2]*pp[2]
                     + wp[3]*pp[HP]     + wp[4]*pp[HP+1]   + wp[5]*pp[HP+2]
                     + wp[6]*pp[2*HP]   + wp[7]*pp[2*HP+1] + wp[8]*pp[2*HP+2];
            }
        }
    }
    __syncthreads();
    red[t] = acc;
    __syncthreads();
    if (ph == 0 && act) {
        float s = red[pix] + red[pix+64] + red[pix+128] + red[pix+192] + bias[o];
        out[(size_t)o * npix + pix] = lrelu(s);
    }
}

// -------- c1 = W1[:,32:] @ feat + b1 -------------------------------------------------
__global__ void k_c1(const float* __restrict__ w1, const float* __restrict__ b1,
                     const float* __restrict__ feat, float* __restrict__ c1)
{
    __shared__ float sf[2048];
    for (int i = threadIdx.x; i < 2048; i += 256) sf[i] = feat[i];
    __syncthreads();
    int o = blockIdx.x * 8 + (threadIdx.x >> 5);
    int lane = threadIdx.x & 31;
    const float* row = w1 + (size_t)o * 2080 + 32;
    float s = 0.f;
    for (int k = lane; k < 2048; k += 32) s += row[k] * sf[k];
    #pragma unroll
    for (int off = 16; off; off >>= 1) s += __shfl_xor_sync(0xffffffffu, s, off);
    if (lane == 0) c1[o] = s + b1[o];
}

// -------- separable sin tables -------------------------------------------------------
__global__ void k_tab(const float* __restrict__ w, int ld, const float* __restrict__ base,
                      float* __restrict__ A, float* __restrict__ B, int width)
{
    __shared__ float s[16];
    int i = blockIdx.x;
    if (threadIdx.x < 16) {
        double arg = (double)(i - 128) * 3.14159265358979323846 / 256.0
                   * exp2((double)threadIdx.x * 0.5);
        s[threadIdx.x] = (float)sin(arg);
    }
    __syncthreads();
    for (int o = threadIdx.x; o < width; o += 256) {
        const float* wr = w + (size_t)o * ld;
        float sa = base[o], sb = 0.f;
        #pragma unroll
        for (int f = 0; f < 16; ++f) {
            sa += s[f] * wr[2 * f];
            sb += s[f] * wr[2 * f + 1];
        }
        A[(size_t)i * width + o] = sa;
        B[(size_t)i * width + o] = sb;
    }
}

// -------- weight-norm ----------------------------------------------------------------
__global__ void k_wnorm(const float* __restrict__ v, const float* __restrict__ g,
                        float* __restrict__ out, int N, int K)
{
    __shared__ float red[256];
    int b = blockIdx.x;
    const float* vr = v + (size_t)b * K;
    float ss = 0.f;
    for (int k = threadIdx.x; k < K; k += 256) { float t = vr[k]; ss += t * t; }
    red[threadIdx.x] = ss;
    __syncthreads();
    for (int off = 128; off; off >>= 1) {
        if (threadIdx.x < off) red[threadIdx.x] += red[threadIdx.x + off];
        __syncthreads();
    }
    float sc = g[b] / sqrtf(red[0]);
    float* orow = out + (size_t)b * K;
    for (int k = threadIdx.x; k < K; k += 256) orow[k] = vr[k] * sc;
}

// -------- mid init: lrelu(A1[i]+B1[j]) -----------------------------------------------
__global__ void k_midinit(const float* __restrict__ A, const float* __restrict__ B,
                          float* __restrict__ mid)
{
    size_t idx = (size_t)blockIdx.x * 256 + threadIdx.x;
    int r = (int)(idx >> 10), o = (int)(idx & 1023);
    int i = r >> 8, j = r & 255;
    mid[idx] = lrelu(A[(size_t)i * 1024 + o] + B[(size_t)j * 1024 + o]);
}

// -------- tf32 GEMM, 2-stage cp.async pipeline, CTA 128x128, warp 64x32 --------------
// mode 1: out[r][n] += lrelu(acc + bias[n])
// mode 2: out[r][n]  = lrelu(acc + tA[i][n] + tB[j][n])
__global__ void __launch_bounds__(256, 2)
k_gemm(const float* __restrict__ X, int ldx, const float* __restrict__ W, int ldw,
       const float* __restrict__ bias, float* __restrict__ out, int ldo,
       int N, int K, int mode, const float* __restrict__ tA, const float* __restrict__ tB)
{
    __shared__ float sA[2][128 * 20];
    __shared__ float sB[2][128 * 20];
    const int tid = threadIdx.x;
    const int m0 = blockIdx.y * 128, n0 = blockIdx.x * 128;
    const int wid = tid >> 5, lane = tid & 31;
    const int wm = wid & 1, wn = wid >> 1;       // 2 m-warps x 4 n-warps
    const int gq = lane >> 2, tq = lane & 3;

    // cp.async addressing: each thread copies 16B for rows lr and lr+64 of A and B
    const int lr = tid >> 2;
    const int lc = (tid & 3) << 2;
    const float* Xp = X + (size_t)(m0 + lr) * ldx + lc;
    const float* Wp = W + (size_t)(n0 + lr) * ldw + lc;
    const uint32_t sAu = (uint32_t)__cvta_generic_to_shared(&sA[0][0]);
    const uint32_t sBu = (uint32_t)__cvta_generic_to_shared(&sB[0][0]);
    const uint32_t stO = (uint32_t)(lr * 20 + lc) * 4;
    const uint32_t stageB = 128u * 20u * 4u;
    const uint32_t rowsk = 64u * 20u * 4u;

    float c[4][4][4];
    #pragma unroll
    for (int a = 0; a < 4; ++a)
        #pragma unroll
        for (int b = 0; b < 4; ++b)
            #pragma unroll
            for (int e = 0; e < 4; ++e) c[a][b][e] = 0.f;

    const int T = K >> 4;

    // prologue: stage 0
    {
        cp16(sAu + stO, Xp);
        cp16(sAu + rowsk + stO, Xp + (size_t)64 * ldx);
        cp16(sBu + stO, Wp);
        cp16(sBu + rowsk + stO, Wp + (size_t)64 * ldw);
        cp_commit();
    }

    for (int it = 0; it < T; ++it) {
        if (it + 1 < T) {
            const int kt = (it + 1) << 4;
            const uint32_t so = (uint32_t)((it + 1) & 1) * stageB;
            cp16(sAu + so + stO, Xp + kt);
            cp16(sAu + so + rowsk + stO, Xp + (size_t)64 * ldx + kt);
            cp16(sBu + so + stO, Wp + kt);
            cp16(sBu + so + rowsk + stO, Wp + (size_t)64 * ldw + kt);
            cp_commit();
            cp_wait1();
        } else {
            cp_wait0();
        }
        __syncthreads();

        const float* A = sA[it & 1];
        const float* B = sB[it & 1];
        #pragma unroll
        for (int ks = 0; ks < 16; ks += 8) {
            uint32_t au[4][4], bu[4][2];
            #pragma unroll
            for (int mf = 0; mf < 4; ++mf) {
                const int rb = (wm * 64 + mf * 16 + gq) * 20 + ks + tq;
                au[mf][0] = rna(A[rb]);
                au[mf][1] = rna(A[rb + 8 * 20]);
                au[mf][2] = rna(A[rb + 4]);
                au[mf][3] = rna(A[rb + 8 * 20 + 4]);
            }
            #pragma unroll
            for (int nf = 0; nf < 4; ++nf) {
                const int rb = (wn * 32 + nf * 8 + gq) * 20 + ks + tq;
                bu[nf][0] = rna(B[rb]);
                bu[nf][1] = rna(B[rb + 4]);
            }
            #pragma unroll
            for (int mf = 0; mf < 4; ++mf)
                #pragma unroll
                for (int nf = 0; nf < 4; ++nf)
                    mma_tf32(c[mf][nf], au[mf], bu[nf]);
        }
        __syncthreads();
    }

    // epilogue
    if (mode == 1) {
        #pragma unroll
        for (int mf = 0; mf < 4; ++mf) {
            const int r0 = m0 + wm * 64 + mf * 16 + gq;
            #pragma unroll
            for (int nf = 0; nf < 4; ++nf) {
                const int cn = n0 + wn * 32 + nf * 8 + tq * 2;
                const float b0v = __ldg(bias + cn);
                const float b1v = __ldg(bias + cn + 1);
                float* p0 = out + (size_t)r0 * ldo + cn;
                float* p1 = p0 + (size_t)8 * ldo;
                float2 o0 = *(float2*)p0;
                o0.x += lrelu(c[mf][nf][0] + b0v);
                o0.y += lrelu(c[mf][nf][1] + b1v);
                *(float2*)p0 = o0;
                float2 o1 = *(float2*)p1;
                o1.x += lrelu(c[mf][nf][2] + b0v);
                o1.y += lrelu(c[mf][nf][3] + b1v);
                *(float2*)p1 = o1;
            }
        }
    } else {
        const int i = m0 >> 8;
        #pragma unroll
        for (int mf = 0; mf < 4; ++mf) {
            const int r0 = m0 + wm * 64 + mf * 16 + gq;
            const int j0 = r0 & 255, j1 = (r0 + 8) & 255;
            #pragma unroll
            for (int nf = 0; nf < 4; ++nf) {
                const int cn = n0 + wn * 32 + nf * 8 + tq * 2;
                const float ta0 = tA[(size_t)i * N + cn];
                const float ta1 = tA[(size_t)i * N + cn + 1];
                float* p0 = out + (size_t)r0 * ldo + cn;
                float* p1 = p0 + (size_t)8 * ldo;
                float2 o0, o1;
                o0.x = lrelu(c[mf][nf][0] + ta0 + tB[(size_t)j0 * N + cn]);
                o0.y = lrelu(c[mf][nf][1] + ta1 + tB[(size_t)j0 * N + cn + 1]);
                o1.x = lrelu(c[mf][nf][2] + ta0 + tB[(size_t)j1 * N + cn]);
                o1.y = lrelu(c[mf][nf][3] + ta1 + tB[(size_t)j1 * N + cn + 1]);
                *(float2*)p0 = o0;
                *(float2*)p1 = o1;
            }
        }
    }
}

// -------- final: sigmoid(h @ w3.T + b3)*1.1-0.05, CHW --------------------------------
__global__ void k_final(const float* __restrict__ h, const float* __restrict__ w3,
                        const float* __restrict__ b3, float* __restrict__ out)
{
    __shared__ float w3s[3 * 512];
    for (int i = threadIdx.x; i < 1536; i += 256) w3s[i] = w3[i];
    __syncthreads();
    int pix = blockIdx.x * 8 + (threadIdx.x >> 5);
    int lane = threadIdx.x & 31;
    const float* hr = h + (size_t)pix * 512;
    float a0 = 0.f, a1 = 0.f, a2 = 0.f;
    for (int k = lane; k < 512; k += 32) {
        float hv = hr[k];
        a0 += hv * w3s[k];
        a1 += hv * w3s[512 + k];
        a2 += hv * w3s[1024 + k];
    }
    #pragma unroll
    for (int off = 16; off; off >>= 1) {
        a0 += __shfl_xor_sync(0xffffffffu, a0, off);
        a1 += __shfl_xor_sync(0xffffffffu, a1, off);
        a2 += __shfl_xor_sync(0xffffffffu, a2, off);
    }
    if (lane == 0) {
        float z[3] = {a0 + b3[0], a1 + b3[1], a2 + b3[2]};
        #pragma unroll
        for (int cch = 0; cch < 3; ++cch) {
            float s = 1.f / (1.f + expf(-z[cch]));
            out[(size_t)cch * NROW + pix] = s * 1.1f - 0.05f;
        }
    }
}

extern "C" void kernel_launch(void* const* d_in, const int* in_sizes, int n_in,
                              void* d_out, int out_size)
{
    (void)in_sizes; (void)n_in; (void)out_size;
    const float* feature = (const float*)d_in[0];
    const float *cw1=(const float*)d_in[1], *cb1=(const float*)d_in[2];
    const float *cw2=(const float*)d_in[3], *cb2=(const float*)d_in[4];
    const float *cw3=(const float*)d_in[5], *cb3=(const float*)d_in[6];
    const float *cw4=(const float*)d_in[7], *cb4=(const float*)d_in[8];
    const float *cw5=(const float*)d_in[9], *cb5=(const float*)d_in[10];
    const float *w1=(const float*)d_in[11], *b1=(const float*)d_in[12];
    const float *m1_vf=(const float*)d_in[13], *m1_gf=(const float*)d_in[14], *m1_bf=(const float*)d_in[15];
    const float *m1_vg=(const float*)d_in[16], *m1_gg=(const float*)d_in[17], *m1_bg=(const float*)d_in[18];
    const float *w2=(const float*)d_in[19], *b2=(const float*)d_in[20];
    const float *m2_vf=(const float*)d_in[21], *m2_gf=(const float*)d_in[22], *m2_bf=(const float*)d_in[23];
    const float *m2_vg=(const float*)d_in[24], *m2_gg=(const float*)d_in[25], *m2_bg=(const float*)d_in[26];
    const float *w3=(const float*)d_in[27], *b3=(const float*)d_in[28];
    float* out = (float*)d_out;

    float *cb0p, *cb1p, *featp, *c1p, *A1p, *B1p, *A2p, *B2p;
    float *w1F, *w1G, *w2F, *w2G, *midp, *hp;
    cudaGetSymbolAddress((void**)&cb0p, g_cbuf0);
    cudaGetSymbolAddress((void**)&cb1p, g_cbuf1);
    cudaGetSymbolAddress((void**)&featp, g_feat);
    cudaGetSymbolAddress((void**)&c1p, g_c1);
    cudaGetSymbolAddress((void**)&A1p, g_A1);
    cudaGetSymbolAddress((void**)&B1p, g_B1);
    cudaGetSymbolAddress((void**)&A2p, g_A2);
    cudaGetSymbolAddress((void**)&B2p, g_B2);
    cudaGetSymbolAddress((void**)&w1F, g_wm1F);
    cudaGetSymbolAddress((void**)&w1G, g_wm1G);
    cudaGetSymbolAddress((void**)&w2F, g_wm2F);
    cudaGetSymbolAddress((void**)&w2G, g_wm2G);
    cudaGetSymbolAddress((void**)&midp, g_mid);
    cudaGetSymbolAddress((void**)&hp, g_h);

    k_conv<<<768, 256>>>(feature, cw1, cb1, cb0p, 448, 192, 8, 8, 1);
    k_conv<<<768, 256>>>(cb0p, cw2, cb2, cb1p, 256, 256, 8, 8, 1);
    k_conv<<<768, 256>>>(cb1p, cw3, cb3, cb0p, 384, 384, 8, 8, 1);
    k_conv<<<768, 256>>>(cb0p, cw4, cb4, cb1p, 256, 256, 8, 6, 0);
    k_conv<<<128, 256>>>(cb1p, cw5, cb5, featp, 768, 128, 6, 4, 0);

    k_c1<<<128, 256>>>(w1, b1, featp, c1p);
    k_tab<<<256, 256>>>(w1, 2080, c1p, A1p, B1p, 1024);
    k_tab<<<256, 256>>>(w2, 1056, b2, A2p, B2p, 512);

    k_wnorm<<<8 * 512, 256>>>(m1_vf, m1_gf, w1F, 512, 512);
    k_wnorm<<<8 * 512, 256>>>(m1_vg, m1_gg, w1G, 512, 512);
    k_wnorm<<<8 * 256, 256>>>(m2_vf, m2_gf, w2F, 256, 256);
    k_wnorm<<<8 * 256, 256>>>(m2_vg, m2_gg, w2G, 256, 256);

    k_midinit<<<(NROW * 1024) / 256, 256>>>(A1p, B1p, midp);

    dim3 blk(256);
    dim3 g512(4, 512), g256(2, 512);
    for (int l = 0; l < 8; ++l) {
        k_gemm<<<g512, blk>>>(midp + 512, 1024, w1F + (size_t)l * 512 * 512, 512,
                              m1_bf + l * 512, midp, 1024, 512, 512, 1, nullptr, nullptr);
        k_gemm<<<g512, blk>>>(midp, 1024, w1G + (size_t)l * 512 * 512, 512,
                              m1_bg + l * 512, midp + 512, 1024, 512, 512, 1, nullptr, nullptr);
    }
    k_gemm<<<g512, blk>>>(midp, 1024, w2 + 32, 1056, nullptr, hp, 512,
                          512, 1024, 2, A2p, B2p);
    for (int l = 0; l < 8; ++l) {
        k_gemm<<<g256, blk>>>(hp + 256, 512, w2F + (size_t)l * 256 * 256, 256,
                              m2_bf + l * 256, hp, 512, 256, 256, 1, nullptr, nullptr);
        k_gemm<<<g256, blk>>>(hp, 512, w2G + (size_t)l * 256 * 256, 256,
                              m2_bg + l * 256, hp + 256, 512, 256, 256, 1, nullptr, nullptr);
    }
    k_final<<<NROW / 8, 256>>>(hp, w3, b3, out);
}